// round 15
// baseline (speedup 1.0000x reference)
#include <cuda_runtime.h>
#include <cuda_fp16.h>
#include <cstdint>

#define Q    2048
#define H    2048
#define NH   16
#define NKV  8
#define HD   128
#define PAST 2048
#define KVLEN (PAST + Q)
#define KEPS 1e-6f

typedef __half h16;

// ---------------- scratch (no allocation allowed) ----------------
__device__ h16 g_hs_h[Q * H];
__device__ h16 g_wq_h[NH * HD * H];
__device__ h16 g_wk_h[NKV * HD * H];
__device__ h16 g_wv_h[NKV * HD * H];
__device__ h16 g_wo_h[NH * HD * NH * HD];
__device__ h16 g_q_h[NH * Q * HD];
__device__ h16 g_k_h[NKV * KVLEN * HD];
__device__ h16 g_v_h[NKV * KVLEN * HD];
__device__ h16 g_ao_h[Q * NH * HD];

// ---------------- helpers ----------------
__device__ __forceinline__ uint32_t smem_u32(const void* p) {
    uint32_t a;
    asm("{ .reg .u64 t; cvta.to.shared.u64 t, %1; cvt.u32.u64 %0, t; }" : "=r"(a) : "l"(p));
    return a;
}
__device__ __forceinline__ uint32_t packh(h16 a, h16 b) {
    return (uint32_t)__half_as_ushort(a) | ((uint32_t)__half_as_ushort(b) << 16);
}
__device__ __forceinline__ uint32_t cvt2h(float a, float b) {
    return packh(__float2half_rn(a), __float2half_rn(b));
}
__device__ __forceinline__ void ldsm4(uint32_t* r, uint32_t addr) {
    asm volatile("ldmatrix.sync.aligned.m8n8.x4.shared.b16 {%0,%1,%2,%3}, [%4];"
                 : "=r"(r[0]), "=r"(r[1]), "=r"(r[2]), "=r"(r[3]) : "r"(addr));
}
__device__ __forceinline__ void ldsm4t(uint32_t* r, uint32_t addr) {
    asm volatile("ldmatrix.sync.aligned.m8n8.x4.trans.shared.b16 {%0,%1,%2,%3}, [%4];"
                 : "=r"(r[0]), "=r"(r[1]), "=r"(r[2]), "=r"(r[3]) : "r"(addr));
}
__device__ __forceinline__ void mma_f16(float* c, const uint32_t* a, const uint32_t* b) {
    asm volatile(
        "mma.sync.aligned.m16n8k16.row.col.f32.f16.f16.f32 "
        "{%0,%1,%2,%3}, {%4,%5,%6,%7}, {%8,%9}, {%0,%1,%2,%3};"
        : "+f"(c[0]), "+f"(c[1]), "+f"(c[2]), "+f"(c[3])
        : "r"(a[0]), "r"(a[1]), "r"(a[2]), "r"(a[3]), "r"(b[0]), "r"(b[1]));
}
__device__ __forceinline__ void cp16(uint32_t dst, const void* src) {
    asm volatile("cp.async.cg.shared.global [%0], [%1], 16;"
                 :: "r"(dst), "l"(__cvta_generic_to_global(src)));
}
__device__ __forceinline__ void cpcommit() { asm volatile("cp.async.commit_group;"); }
template <int N>
__device__ __forceinline__ void cpwait() {
    asm volatile("cp.async.wait_group %0;" :: "n"(N));
}
__device__ __forceinline__ float ex2(float x) {
    float y;
    asm("ex2.approx.f32 %0, %1;" : "=f"(y) : "f"(x));
    return y;
}

// ---------------- merged convert kernel (8 float4 / thread, all single-plane) ----------------
__device__ __forceinline__ void kconv_body(
    int b, int tid,
    const float* hs, h16* hsh, const float* wq, h16* wqh,
    const float* wk, h16* wkh, const float* wv, h16* wvh,
    const float* wo, h16* woh,
    const float* pk, h16* kch, const float* pv, h16* vch)
{
    if (b >= 16384) {   // caches (strided dst)
        b -= 16384;
        const float* x;
        h16* dst;
        if (b < 2048) { x = pk; dst = kch; }
        else          { x = pv; dst = vch; b -= 2048; }
        int i = b * 256 + tid;
        int e = i * 4;
        int kv = e / (PAST * HD);
        int rem = e - kv * (PAST * HD);
        size_t de = (size_t)kv * (KVLEN * HD) + rem;
        float4 v = ((const float4*)x)[i];
        *(uint32_t*)(dst + de)     = cvt2h(v.x, v.y);
        *(uint32_t*)(dst + de + 2) = cvt2h(v.z, v.w);
        return;
    }
    const float* src;
    h16* dst;
    int base;
    if (b < 4096)       { src = hs; dst = hsh; base = 0; }
    else if (b < 8192)  { src = wq; dst = wqh; base = 4096; }
    else if (b < 10240) { src = wk; dst = wkh; base = 8192; }
    else if (b < 12288) { src = wv; dst = wvh; base = 10240; }
    else                { src = wo; dst = woh; base = 12288; }
    int i = (b - base) * 256 + tid;
    float4 v = ((const float4*)src)[i];
    ((uint32_t*)dst)[2 * i]     = cvt2h(v.x, v.y);
    ((uint32_t*)dst)[2 * i + 1] = cvt2h(v.z, v.w);
}

__global__ __launch_bounds__(256) void kconv_all(
    const float* __restrict__ hs, h16* __restrict__ hsh,
    const float* __restrict__ wq, h16* __restrict__ wqh,
    const float* __restrict__ wk, h16* __restrict__ wkh,
    const float* __restrict__ wv, h16* __restrict__ wvh,
    const float* __restrict__ wo, h16* __restrict__ woh,
    const float* __restrict__ pk, h16* __restrict__ kch,
    const float* __restrict__ pv, h16* __restrict__ vch)
{
#pragma unroll
    for (int j = 0; j < 8; j++) {
        kconv_body(blockIdx.x * 8 + j, threadIdx.x,
                   hs, hsh, wq, wqh, wk, wkh, wv, wvh, wo, woh,
                   pk, kch, pv, vch);
    }
}

// ---------------- GEMM constants ----------------
#define ROWB   80
#define PLANEB 10240
#define STAGEB2 20480                 // 2 planes (A128, B128)
#define QKV_SMEM (2048 + 128 * 132 * 4)   // epilogue: red + xs = 69632 (> 2*STAGEB2)

// ---------------- fused QKV projection GEMM + RMSNorm + RoPE epilogue ----------------
// grid (32, 16): bx<16 -> Q head bx, <24 -> K head bx-16, else V head bx-24
__global__ __launch_bounds__(256) void hgemm_qkv(
    const h16* __restrict__ hsh,
    const h16* __restrict__ wqh, const h16* __restrict__ wkh,
    const h16* __restrict__ wvh,
    const float* __restrict__ cosb, const float* __restrict__ sinb,
    const float* __restrict__ qw, const float* __restrict__ kw,
    h16* __restrict__ qh, h16* __restrict__ kh, float* __restrict__ newK,
    float* __restrict__ newV, h16* __restrict__ vph)
{
    extern __shared__ char hsm[];
    const int bx = blockIdx.x;
    const int tid = threadIdx.x;
    const int lane = tid & 31;
    const int wid = tid >> 5;
    const int wm = wid >> 2;
    const int wn = wid & 3;
    const uint32_t base_u = smem_u32(hsm);
    const int K = H;

    const h16* Bh;
    int colb;
    if (bx < 16)      { Bh = wqh; colb = bx * 128; }
    else if (bx < 24) { Bh = wkh; colb = (bx - 16) * 128; }
    else              { Bh = wvh; colb = (bx - 24) * 128; }

    const h16* pl[2] = {
        hsh + (size_t)(blockIdx.y * 128) * K,
        Bh + (size_t)colb * K };

    const int rowselA = lane & 15;
    const int halfA = lane >> 4;
    const int rowselB = (lane & 7) + (lane >> 4) * 8;
    const int halfB = (lane >> 3) & 1;
    const uint32_t aoff0 = (uint32_t)((wm * 64 + rowselA) * ROWB + halfA * 16);
    const uint32_t boff0 = (uint32_t)((wn * 32 + rowselB) * ROWB + halfB * 16);

    float acc[4][4][4];
#pragma unroll
    for (int i = 0; i < 4; i++)
#pragma unroll
        for (int j = 0; j < 4; j++)
#pragma unroll
            for (int r = 0; r < 4; r++) acc[i][j][r] = 0.0f;

    const int nst = K / 32;
    {
        uint32_t dstb = base_u;
        for (int i = tid; i < 1024; i += 256) {
            int p = i >> 9, row = (i >> 2) & 127, seg = i & 3;
            cp16(dstb + p * PLANEB + row * ROWB + seg * 16,
                 pl[p] + (size_t)row * K + seg * 8);
        }
        cpcommit();
    }

    for (int s = 0; s < nst; s++) {
        cpwait<0>();
        __syncthreads();
        if (s + 1 < nst) {
            int kt = (s + 1) * 32;
            uint32_t dstb = base_u + ((s + 1) & 1) * STAGEB2;
            for (int i = tid; i < 1024; i += 256) {
                int p = i >> 9, row = (i >> 2) & 127, seg = i & 3;
                cp16(dstb + p * PLANEB + row * ROWB + seg * 16,
                     pl[p] + (size_t)row * K + kt + seg * 8);
            }
            cpcommit();
        }
        const uint32_t sb = base_u + (s & 1) * STAGEB2;
#pragma unroll
        for (int kc = 0; kc < 2; kc++) {
            uint32_t ah[4][4];
#pragma unroll
            for (int mi = 0; mi < 4; mi++)
                ldsm4(ah[mi], sb + aoff0 + mi * (16 * ROWB) + kc * 32);
            uint32_t bh[4][2];
#pragma unroll
            for (int p = 0; p < 2; p++) {
                uint32_t r[4];
                ldsm4(r, sb + PLANEB + boff0 + p * (16 * ROWB) + kc * 32);
                bh[2 * p][0] = r[0]; bh[2 * p][1] = r[1];
                bh[2 * p + 1][0] = r[2]; bh[2 * p + 1][1] = r[3];
            }
#pragma unroll
            for (int mi = 0; mi < 4; mi++)
#pragma unroll
                for (int nj = 0; nj < 4; nj++)
                    mma_f16(acc[mi][nj], ah[mi], bh[nj]);
        }
    }

    const int rfrag = lane >> 2;
    const int cpair = (lane & 3) * 2;

    if (bx < 24) {
        // ---- fused RMSNorm + RoPE epilogue (one head per CTA col-block) ----
        __syncthreads();   // done with stage buffers; reuse smem
        float* red = (float*)hsm;               // [128][4] = 2048 B
        float* xs  = (float*)(hsm + 2048);      // [128] rows, stride 132 floats
        const float* w = (bx < 16) ? qw : kw;

#pragma unroll
        for (int mi = 0; mi < 4; mi++) {
#pragma unroll
            for (int half = 0; half < 2; half++) {
                float sq = 0.0f;
#pragma unroll
                for (int nj = 0; nj < 4; nj++) {
                    float a0 = acc[mi][nj][2 * half], a1 = acc[mi][nj][2 * half + 1];
                    sq += a0 * a0 + a1 * a1;
                }
                sq += __shfl_xor_sync(0xffffffffu, sq, 1);
                sq += __shfl_xor_sync(0xffffffffu, sq, 2);
                if ((lane & 3) == 0) {
                    int rloc = wm * 64 + mi * 16 + half * 8 + rfrag;
                    red[rloc * 4 + wn] = sq;
                }
            }
        }
        __syncthreads();

#pragma unroll
        for (int mi = 0; mi < 4; mi++) {
#pragma unroll
            for (int half = 0; half < 2; half++) {
                int rloc = wm * 64 + mi * 16 + half * 8 + rfrag;
                float sum = red[rloc * 4 + 0] + red[rloc * 4 + 1]
                          + red[rloc * 4 + 2] + red[rloc * 4 + 3];
                float rs = rsqrtf(sum * (1.0f / HD) + KEPS);
#pragma unroll
                for (int nj = 0; nj < 4; nj++) {
                    int d = wn * 32 + nj * 8 + cpair;
                    float v0 = acc[mi][nj][2 * half]     * rs * w[d];
                    float v1 = acc[mi][nj][2 * half + 1] * rs * w[d + 1];
                    acc[mi][nj][2 * half]     = v0;
                    acc[mi][nj][2 * half + 1] = v1;
                    xs[rloc * 132 + d]     = v0;
                    xs[rloc * 132 + d + 1] = v1;
                }
            }
        }
        __syncthreads();

        const float QSC = 0.08838834764831845f * 1.44269504088896341f;
#pragma unroll
        for (int mi = 0; mi < 4; mi++) {
#pragma unroll
            for (int half = 0; half < 2; half++) {
                int rloc = wm * 64 + mi * 16 + half * 8 + rfrag;
                int srow = blockIdx.y * 128 + rloc;
#pragma unroll
                for (int nj = 0; nj < 4; nj++) {
                    int d = wn * 32 + nj * 8 + cpair;
                    float2 cc = *(const float2*)(cosb + (size_t)srow * HD + d);
                    float2 ss = *(const float2*)(sinb + (size_t)srow * HD + d);
                    float p0 = xs[rloc * 132 + (d ^ 64)];
                    float p1 = xs[rloc * 132 + ((d ^ 64) + 1)];
                    float sgn = (d < 64) ? -1.0f : 1.0f;
                    float o0 = acc[mi][nj][2 * half]     * cc.x + sgn * p0 * ss.x;
                    float o1 = acc[mi][nj][2 * half + 1] * cc.y + sgn * p1 * ss.y;
                    if (bx < 16) {
                        *(uint32_t*)(qh + ((size_t)bx * Q + srow) * HD + d) =
                            cvt2h(o0 * QSC, o1 * QSC);
                    } else {
                        int kv = bx - 16;
                        *(float2*)(newK + ((size_t)kv * Q + srow) * HD + d) =
                            make_float2(o0, o1);
                        *(uint32_t*)(kh + ((size_t)kv * KVLEN + PAST + srow) * HD + d) =
                            cvt2h(o0, o1);
                    }
                }
            }
        }
    } else {
        // ---- V epilogue ----
#pragma unroll
        for (int mi = 0; mi < 4; mi++) {
#pragma unroll
            for (int nj = 0; nj < 4; nj++) {
                int d = wn * 32 + nj * 8 + cpair;
#pragma unroll
                for (int half = 0; half < 2; half++) {
                    int rowg = blockIdx.y * 128 + wm * 64 + mi * 16 + rfrag + half * 8;
                    float2 v = make_float2(acc[mi][nj][2 * half], acc[mi][nj][2 * half + 1]);
                    int kv = bx - 24;
                    *(float2*)(newV + (size_t)kv * (Q * HD) + (size_t)rowg * HD + d) = v;
                    size_t de = (size_t)kv * (KVLEN * HD) + (size_t)(PAST + rowg) * HD + d;
                    *(uint32_t*)(vph + de) = cvt2h(v.x, v.y);
                }
            }
        }
    }
}

// ---------------- output projection GEMM: 64x128 tiles, 512 CTAs ----------------
#define O_APLANE 5120                 // 64 rows * 80B
#define O_STAGE (O_APLANE + PLANEB)   // 15360
#define HO_SMEM (2 * O_STAGE)         // 30720

__global__ __launch_bounds__(256) void hgemm_o(
    const h16* __restrict__ Ah, const h16* __restrict__ Bh,
    float* __restrict__ C)
{
    extern __shared__ char hsm[];
    const int tid = threadIdx.x;
    const int lane = tid & 31;
    const int wid = tid >> 5;
    const int wm = wid >> 2;      // 0..1 -> 32 rows each
    const int wn = wid & 3;       // 0..3 -> 32 cols each
    const uint32_t base_u = smem_u32(hsm);
    const int K = NH * HD, N = NH * HD;

    const h16* Ap = Ah + (size_t)(blockIdx.y * 64) * K;
    const h16* Bp = Bh + (size_t)(blockIdx.x * 128) * K;

    const int rowselA = lane & 15;
    const int halfA = lane >> 4;
    const int rowselB = (lane & 7) + (lane >> 4) * 8;
    const int halfB = (lane >> 3) & 1;
    const uint32_t aoff0 = (uint32_t)((wm * 32 + rowselA) * ROWB + halfA * 16);
    const uint32_t boff0 = (uint32_t)(O_APLANE + (wn * 32 + rowselB) * ROWB + halfB * 16);

    float acc[2][4][4];
#pragma unroll
    for (int i = 0; i < 2; i++)
#pragma unroll
        for (int j = 0; j < 4; j++)
#pragma unroll
            for (int r = 0; r < 4; r++) acc[i][j][r] = 0.0f;

    const int nst = K / 32;
    {
        uint32_t dstb = base_u;
        for (int i = tid; i < 768; i += 256) {
            if (i < 256) {
                int row = i >> 2, seg = i & 3;
                cp16(dstb + row * ROWB + seg * 16, Ap + (size_t)row * K + seg * 8);
            } else {
                int j = i - 256, row = j >> 2, seg = j & 3;
                cp16(dstb + O_APLANE + row * ROWB + seg * 16,
                     Bp + (size_t)row * K + seg * 8);
            }
        }
        cpcommit();
    }

    for (int s = 0; s < nst; s++) {
        cpwait<0>();
        __syncthreads();
        if (s + 1 < nst) {
            int kt = (s + 1) * 32;
            uint32_t dstb = base_u + ((s + 1) & 1) * O_STAGE;
            for (int i = tid; i < 768; i += 256) {
                if (i < 256) {
                    int row = i >> 2, seg = i & 3;
                    cp16(dstb + row * ROWB + seg * 16,
                         Ap + (size_t)row * K + kt + seg * 8);
                } else {
                    int j = i - 256, row = j >> 2, seg = j & 3;
                    cp16(dstb + O_APLANE + row * ROWB + seg * 16,
                         Bp + (size_t)row * K + kt + seg * 8);
                }
            }
            cpcommit();
        }
        const uint32_t sb = base_u + (s & 1) * O_STAGE;
#pragma unroll
        for (int kc = 0; kc < 2; kc++) {
            uint32_t ah[2][4];
#pragma unroll
            for (int mi = 0; mi < 2; mi++)
                ldsm4(ah[mi], sb + aoff0 + mi * (16 * ROWB) + kc * 32);
            uint32_t bh[4][2];
#pragma unroll
            for (int p = 0; p < 2; p++) {
                uint32_t r[4];
                ldsm4(r, sb + boff0 + p * (16 * ROWB) + kc * 32);
                bh[2 * p][0] = r[0]; bh[2 * p][1] = r[1];
                bh[2 * p + 1][0] = r[2]; bh[2 * p + 1][1] = r[3];
            }
#pragma unroll
            for (int mi = 0; mi < 2; mi++)
#pragma unroll
                for (int nj = 0; nj < 4; nj++)
                    mma_f16(acc[mi][nj], ah[mi], bh[nj]);
        }
    }

    const int rfrag = lane >> 2;
    const int cpair = (lane & 3) * 2;
#pragma unroll
    for (int mi = 0; mi < 2; mi++) {
#pragma unroll
        for (int nj = 0; nj < 4; nj++) {
            int colg = blockIdx.x * 128 + wn * 32 + nj * 8 + cpair;
#pragma unroll
            for (int half = 0; half < 2; half++) {
                int rowg = blockIdx.y * 64 + wm * 32 + mi * 16 + rfrag + half * 8;
                *(float2*)(C + (size_t)rowg * N + colg) =
                    make_float2(acc[mi][nj][2 * half], acc[mi][nj][2 * half + 1]);
            }
        }
    }
}

// ---------------- Flash attention: TQ=64, 128 threads, 2 CTAs/SM ----------------
#define AT_TQ 64
#define AT_TK 64
#define KVROW 272
#define KVPLANE (64 * KVROW)
#define TILEBUF (2 * KVPLANE)
#define AT_SMEM (2 * TILEBUF)

__global__ __launch_bounds__(128, 2) void attn_mma(
    const h16* __restrict__ qh,
    const h16* __restrict__ kch, const h16* __restrict__ vch,
    h16* __restrict__ aoh)
{
    extern __shared__ char asmem[];
    const int h = blockIdx.x;
    const int q0 = ((int)gridDim.y - 1 - (int)blockIdx.y) * AT_TQ;  // largest-first
    const int kvh = h >> 1;
    const int tid = threadIdx.x;
    const int lane = tid & 31;
    const int wid = tid >> 5;
    const uint32_t sb = smem_u32(asmem);

    {
        const h16* qsrc = qh + ((size_t)h * Q + q0) * HD;
        for (int i = tid; i < 1024; i += 128) {
            int row = i >> 4, seg = i & 15;
            cp16(sb + row * KVROW + seg * 16, qsrc + (size_t)row * HD + seg * 8);
        }
        cpcommit();
        cpwait<0>();
        __syncthreads();
    }
    uint32_t aQh[8][4];
    {
        uint32_t a0 = sb + (wid * 16 + (lane & 15)) * KVROW + (lane >> 4) * 16;
#pragma unroll
        for (int kc = 0; kc < 8; kc++)
            ldsm4(aQh[kc], a0 + kc * 32);
    }
    __syncthreads();

    float oacc[16][4];
#pragma unroll
    for (int f = 0; f < 16; f++)
#pragma unroll
        for (int r = 0; r < 4; r++) oacc[f][r] = 0.0f;
    float m0 = -1e30f, m1 = -1e30f, l0 = 0.0f, l1 = 0.0f;

    const int nt = (PAST + q0 + AT_TQ) / AT_TK;
    const h16* ksrc = kch + (size_t)kvh * KVLEN * HD;
    const h16* vsrc = vch + (size_t)kvh * KVLEN * HD;

    {
        for (int i = tid; i < 2048; i += 128) {
            int p = i >> 10, row = (i >> 4) & 63, seg = i & 15;
            const h16* s0 = p ? vsrc : ksrc;
            cp16(sb + p * KVPLANE + row * KVROW + seg * 16,
                 s0 + (size_t)row * HD + seg * 8);
        }
        cpcommit();
    }

    const int rowselB = (lane & 7) + (lane >> 4) * 8;
    const int halfB = (lane >> 3) & 1;
    const int rowV = lane & 15;
    const int halfV = (lane >> 4) * 16;

    for (int t = 0; t < nt; t++) {
        __syncthreads();
        if (t + 1 < nt) {
            int j1 = (t + 1) * AT_TK;
            uint32_t db = sb + ((t + 1) & 1) * TILEBUF;
            for (int i = tid; i < 2048; i += 128) {
                int p = i >> 10, row = (i >> 4) & 63, seg = i & 15;
                const h16* s0 = p ? vsrc : ksrc;
                cp16(db + p * KVPLANE + row * KVROW + seg * 16,
                     s0 + (size_t)(j1 + row) * HD + seg * 8);
            }
            cpcommit();
            cpwait<1>();
        } else {
            cpwait<0>();
        }
        __syncthreads();

        const uint32_t kb = sb + (t & 1) * TILEBUF;
        const int j0 = t * AT_TK;

        float sacc[8][4];
#pragma unroll
        for (int j = 0; j < 8; j++)
#pragma unroll
            for (int r = 0; r < 4; r++) sacc[j][r] = 0.0f;
#pragma unroll
        for (int kc = 0; kc < 8; kc++) {
#pragma unroll
            for (int nj = 0; nj < 4; nj++) {
                uint32_t kh[4];
                ldsm4(kh, kb + (nj * 16 + rowselB) * KVROW + halfB * 16 + kc * 32);
                mma_f16(sacc[2 * nj],     aQh[kc], kh);
                mma_f16(sacc[2 * nj + 1], aQh[kc], kh + 2);
            }
        }

        if (j0 + AT_TK - 1 > PAST + q0 + wid * 16) {
            int r0g = PAST + q0 + wid * 16 + (lane >> 2);
#pragma unroll
            for (int j = 0; j < 8; j++) {
                int cg = j0 + j * 8 + (lane & 3) * 2;
                if (cg > r0g)     sacc[j][0] = -1e30f;
                if (cg + 1 > r0g) sacc[j][1] = -1e30f;
                if (cg > r0g + 8)     sacc[j][2] = -1e30f;
                if (cg + 1 > r0g + 8) sacc[j][3] = -1e30f;
            }
        }

        float t0 = -1e30f, t1 = -1e30f;
#pragma unroll
        for (int j = 0; j < 8; j++) {
            t0 = fmaxf(t0, fmaxf(sacc[j][0], sacc[j][1]));
            t1 = fmaxf(t1, fmaxf(sacc[j][2], sacc[j][3]));
        }
        t0 = fmaxf(t0, __shfl_xor_sync(0xffffffffu, t0, 1));
        t0 = fmaxf(t0, __shfl_xor_sync(0xffffffffu, t0, 2));
        t1 = fmaxf(t1, __shfl_xor_sync(0xffffffffu, t1, 1));
        t1 = fmaxf(t1, __shfl_xor_sync(0xffffffffu, t1, 2));
        float mn0 = fmaxf(m0, t0), mn1 = fmaxf(m1, t1);
        float c0 = ex2(m0 - mn0), c1 = ex2(m1 - mn1);
        m0 = mn0; m1 = mn1;
        float ps0 = 0.0f, ps1 = 0.0f;
#pragma unroll
        for (int j = 0; j < 8; j++) {
            sacc[j][0] = ex2(sacc[j][0] - mn0); ps0 += sacc[j][0];
            sacc[j][1] = ex2(sacc[j][1] - mn0); ps0 += sacc[j][1];
            sacc[j][2] = ex2(sacc[j][2] - mn1); ps1 += sacc[j][2];
            sacc[j][3] = ex2(sacc[j][3] - mn1); ps1 += sacc[j][3];
        }
        ps0 += __shfl_xor_sync(0xffffffffu, ps0, 1);
        ps0 += __shfl_xor_sync(0xffffffffu, ps0, 2);
        ps1 += __shfl_xor_sync(0xffffffffu, ps1, 1);
        ps1 += __shfl_xor_sync(0xffffffffu, ps1, 2);
        l0 = l0 * c0 + ps0;
        l1 = l1 * c1 + ps1;

        unsigned need = __ballot_sync(0xffffffffu, (c0 != 1.0f) || (c1 != 1.0f));
        if (need) {
#pragma unroll
            for (int f = 0; f < 16; f++) {
                oacc[f][0] *= c0; oacc[f][1] *= c0;
                oacc[f][2] *= c1; oacc[f][3] *= c1;
            }
        }

        uint32_t pP[4][4];
#pragma unroll
        for (int kc = 0; kc < 4; kc++) {
            pP[kc][0] = cvt2h(sacc[2 * kc][0],     sacc[2 * kc][1]);
            pP[kc][1] = cvt2h(sacc[2 * kc][2],     sacc[2 * kc][3]);
            pP[kc][2] = cvt2h(sacc[2 * kc + 1][0], sacc[2 * kc + 1][1]);
            pP[kc][3] = cvt2h(sacc[2 * kc + 1][2], sacc[2 * kc + 1][3]);
        }

        const uint32_t vb = kb + KVPLANE;
#pragma unroll
        for (int kc = 0; kc < 4; kc++) {
#pragma unroll
            for (int dj = 0; dj < 8; dj++) {
                uint32_t vh[4];
                ldsm4t(vh, vb + (kc * 16 + rowV) * KVROW + dj * 32 + halfV);
                mma_f16(oacc[2 * dj],     pP[kc], vh);
                mma_f16(oacc[2 * dj + 1], pP[kc], vh + 2);
            }
        }
    }

    float inv0 = 1.0f / l0, inv1 = 1.0f / l1;
    int r0 = q0 + wid * 16 + (lane >> 2);
#pragma unroll
    for (int f = 0; f < 16; f++) {
        int d = f * 8 + (lane & 3) * 2;
        size_t e0 = (size_t)r0 * (NH * HD) + h * HD + d;
        size_t e1 = e0 + (size_t)8 * (NH * HD);
        *(uint32_t*)(aoh + e0) = cvt2h(oacc[f][0] * inv0, oacc[f][1] * inv0);
        *(uint32_t*)(aoh + e1) = cvt2h(oacc[f][2] * inv1, oacc[f][3] * inv1);
    }
}

// ---------------- launch ----------------
extern "C" void kernel_launch(void* const* d_in, const int* in_sizes, int n_in,
                              void* d_out, int out_size)
{
    const float* hs    = (const float*)d_in[0];
    const float* cosb  = (const float*)d_in[1];
    const float* sinb  = (const float*)d_in[2];
    const float* pastK = (const float*)d_in[4];
    const float* pastV = (const float*)d_in[5];
    const float* Wq    = (const float*)d_in[6];
    const float* Wk    = (const float*)d_in[7];
    const float* Wv    = (const float*)d_in[8];
    const float* Wo    = (const float*)d_in[9];
    const float* qw    = (const float*)d_in[10];
    const float* kw    = (const float*)d_in[11];

    float* out  = (float*)d_out;
    float* newK = out + (size_t)Q * NH * HD;
    float* newV = newK + (size_t)NKV * Q * HD;

    h16 *hsh, *wqh, *wkh, *wvh, *woh;
    h16 *qph, *kph, *vph, *aoh;
    cudaGetSymbolAddress((void**)&hsh, g_hs_h);
    cudaGetSymbolAddress((void**)&wqh, g_wq_h);
    cudaGetSymbolAddress((void**)&wkh, g_wk_h);
    cudaGetSymbolAddress((void**)&wvh, g_wv_h);
    cudaGetSymbolAddress((void**)&woh, g_wo_h);
    cudaGetSymbolAddress((void**)&qph, g_q_h);
    cudaGetSymbolAddress((void**)&kph, g_k_h);
    cudaGetSymbolAddress((void**)&vph, g_v_h);
    cudaGetSymbolAddress((void**)&aoh, g_ao_h);

    cudaFuncSetAttribute(hgemm_qkv, cudaFuncAttributeMaxDynamicSharedMemorySize, QKV_SMEM);
    cudaFuncSetAttribute(hgemm_o, cudaFuncAttributeMaxDynamicSharedMemorySize, HO_SMEM);
    cudaFuncSetAttribute(attn_mma, cudaFuncAttributeMaxDynamicSharedMemorySize, AT_SMEM);

    // merged convert (8 virtual blocks per real block)
    kconv_all<<<2560, 256>>>(hs, hsh, Wq, wqh, Wk, wkh, Wv, wvh, Wo, woh,
                             pastK, kph, pastV, vph);

    // fused QKV projection + RMSNorm + RoPE
    hgemm_qkv<<<dim3(32, Q / 128), 256, QKV_SMEM>>>(
        hsh, wqh, wkh, wvh, cosb, sinb, qw, kw, qph, kph, newK, newV, vph);

    // attention (TQ=64, 2 CTAs/SM)
    attn_mma<<<dim3(NH, Q / AT_TQ), 128, AT_SMEM>>>(qph, kph, vph, aoh);

    // output projection (64x128 tiles, 512 CTAs)
    hgemm_o<<<dim3(NH * HD / 128, Q / 64), 256, HO_SMEM>>>(aoh, woh, out);
}

// round 16
// speedup vs baseline: 1.0158x; 1.0158x over previous
#include <cuda_runtime.h>
#include <cuda_fp16.h>
#include <cstdint>

#define Q    2048
#define H    2048
#define NH   16
#define NKV  8
#define HD   128
#define PAST 2048
#define KVLEN (PAST + Q)
#define KEPS 1e-6f

typedef __half h16;

// ---------------- scratch (no allocation allowed) ----------------
__device__ h16 g_hs_h[Q * H];
__device__ h16 g_wq_h[NH * HD * H];
__device__ h16 g_wk_h[NKV * HD * H];
__device__ h16 g_wv_h[NKV * HD * H];
__device__ h16 g_wo_h[NH * HD * NH * HD];
__device__ h16 g_q_h[NH * Q * HD];
__device__ h16 g_k_h[NKV * KVLEN * HD];
__device__ h16 g_v_h[NKV * KVLEN * HD];
__device__ h16 g_ao_h[Q * NH * HD];

// ---------------- helpers ----------------
__device__ __forceinline__ uint32_t smem_u32(const void* p) {
    uint32_t a;
    asm("{ .reg .u64 t; cvta.to.shared.u64 t, %1; cvt.u32.u64 %0, t; }" : "=r"(a) : "l"(p));
    return a;
}
__device__ __forceinline__ uint32_t packh(h16 a, h16 b) {
    return (uint32_t)__half_as_ushort(a) | ((uint32_t)__half_as_ushort(b) << 16);
}
__device__ __forceinline__ uint32_t cvt2h(float a, float b) {
    return packh(__float2half_rn(a), __float2half_rn(b));
}
__device__ __forceinline__ void ldsm4(uint32_t* r, uint32_t addr) {
    asm volatile("ldmatrix.sync.aligned.m8n8.x4.shared.b16 {%0,%1,%2,%3}, [%4];"
                 : "=r"(r[0]), "=r"(r[1]), "=r"(r[2]), "=r"(r[3]) : "r"(addr));
}
__device__ __forceinline__ void ldsm4t(uint32_t* r, uint32_t addr) {
    asm volatile("ldmatrix.sync.aligned.m8n8.x4.trans.shared.b16 {%0,%1,%2,%3}, [%4];"
                 : "=r"(r[0]), "=r"(r[1]), "=r"(r[2]), "=r"(r[3]) : "r"(addr));
}
__device__ __forceinline__ void mma_f16(float* c, const uint32_t* a, const uint32_t* b) {
    asm volatile(
        "mma.sync.aligned.m16n8k16.row.col.f32.f16.f16.f32 "
        "{%0,%1,%2,%3}, {%4,%5,%6,%7}, {%8,%9}, {%0,%1,%2,%3};"
        : "+f"(c[0]), "+f"(c[1]), "+f"(c[2]), "+f"(c[3])
        : "r"(a[0]), "r"(a[1]), "r"(a[2]), "r"(a[3]), "r"(b[0]), "r"(b[1]));
}
__device__ __forceinline__ void cp16(uint32_t dst, const void* src) {
    asm volatile("cp.async.cg.shared.global [%0], [%1], 16;"
                 :: "r"(dst), "l"(__cvta_generic_to_global(src)));
}
__device__ __forceinline__ void cpcommit() { asm volatile("cp.async.commit_group;"); }
template <int N>
__device__ __forceinline__ void cpwait() {
    asm volatile("cp.async.wait_group %0;" :: "n"(N));
}
__device__ __forceinline__ float ex2(float x) {
    float y;
    asm("ex2.approx.f32 %0, %1;" : "=f"(y) : "f"(x));
    return y;
}

// ---------------- merged convert kernel (8 float4 / thread, all single-plane) ----------------
__device__ __forceinline__ void kconv_body(
    int b, int tid,
    const float* hs, h16* hsh, const float* wq, h16* wqh,
    const float* wk, h16* wkh, const float* wv, h16* wvh,
    const float* wo, h16* woh,
    const float* pk, h16* kch, const float* pv, h16* vch)
{
    if (b >= 16384) {   // caches (strided dst)
        b -= 16384;
        const float* x;
        h16* dst;
        if (b < 2048) { x = pk; dst = kch; }
        else          { x = pv; dst = vch; b -= 2048; }
        int i = b * 256 + tid;
        int e = i * 4;
        int kv = e / (PAST * HD);
        int rem = e - kv * (PAST * HD);
        size_t de = (size_t)kv * (KVLEN * HD) + rem;
        float4 v = ((const float4*)x)[i];
        *(uint32_t*)(dst + de)     = cvt2h(v.x, v.y);
        *(uint32_t*)(dst + de + 2) = cvt2h(v.z, v.w);
        return;
    }
    const float* src;
    h16* dst;
    int base;
    if (b < 4096)       { src = hs; dst = hsh; base = 0; }
    else if (b < 8192)  { src = wq; dst = wqh; base = 4096; }
    else if (b < 10240) { src = wk; dst = wkh; base = 8192; }
    else if (b < 12288) { src = wv; dst = wvh; base = 10240; }
    else                { src = wo; dst = woh; base = 12288; }
    int i = (b - base) * 256 + tid;
    float4 v = ((const float4*)src)[i];
    ((uint32_t*)dst)[2 * i]     = cvt2h(v.x, v.y);
    ((uint32_t*)dst)[2 * i + 1] = cvt2h(v.z, v.w);
}

__global__ __launch_bounds__(256) void kconv_all(
    const float* __restrict__ hs, h16* __restrict__ hsh,
    const float* __restrict__ wq, h16* __restrict__ wqh,
    const float* __restrict__ wk, h16* __restrict__ wkh,
    const float* __restrict__ wv, h16* __restrict__ wvh,
    const float* __restrict__ wo, h16* __restrict__ woh,
    const float* __restrict__ pk, h16* __restrict__ kch,
    const float* __restrict__ pv, h16* __restrict__ vch)
{
#pragma unroll
    for (int j = 0; j < 8; j++) {
        kconv_body(blockIdx.x * 8 + j, threadIdx.x,
                   hs, hsh, wq, wqh, wk, wkh, wv, wvh, wo, woh,
                   pk, kch, pv, vch);
    }
}

// ---------------- GEMM constants ----------------
#define ROWB   80
#define PLANEB 10240
#define STAGEB2 20480                 // 2 planes (A, B)
#define HO_SMEM (2 * STAGEB2)         // 40960
#define QKV_SMEM (2048 + 128 * 132 * 4)   // epilogue: red + xs = 69632

// ---------------- fused QKV projection GEMM + RMSNorm + RoPE epilogue ----------------
// grid (32, 16): bx<16 -> Q head bx, <24 -> K head bx-16, else V head bx-24
__global__ __launch_bounds__(256) void hgemm_qkv(
    const h16* __restrict__ hsh,
    const h16* __restrict__ wqh, const h16* __restrict__ wkh,
    const h16* __restrict__ wvh,
    const float* __restrict__ cosb, const float* __restrict__ sinb,
    const float* __restrict__ qw, const float* __restrict__ kw,
    h16* __restrict__ qh, h16* __restrict__ kh, float* __restrict__ newK,
    float* __restrict__ newV, h16* __restrict__ vph)
{
    extern __shared__ char hsm[];
    const int bx = blockIdx.x;
    const int tid = threadIdx.x;
    const int lane = tid & 31;
    const int wid = tid >> 5;
    const int wm = wid >> 2;
    const int wn = wid & 3;
    const uint32_t base_u = smem_u32(hsm);
    const int K = H;

    const h16* Bh;
    int colb;
    if (bx < 16)      { Bh = wqh; colb = bx * 128; }
    else if (bx < 24) { Bh = wkh; colb = (bx - 16) * 128; }
    else              { Bh = wvh; colb = (bx - 24) * 128; }

    const h16* pl[2] = {
        hsh + (size_t)(blockIdx.y * 128) * K,
        Bh + (size_t)colb * K };

    const int rowselA = lane & 15;
    const int halfA = lane >> 4;
    const int rowselB = (lane & 7) + (lane >> 4) * 8;
    const int halfB = (lane >> 3) & 1;
    const uint32_t aoff0 = (uint32_t)((wm * 64 + rowselA) * ROWB + halfA * 16);
    const uint32_t boff0 = (uint32_t)((wn * 32 + rowselB) * ROWB + halfB * 16);

    float acc[4][4][4];
#pragma unroll
    for (int i = 0; i < 4; i++)
#pragma unroll
        for (int j = 0; j < 4; j++)
#pragma unroll
            for (int r = 0; r < 4; r++) acc[i][j][r] = 0.0f;

    const int nst = K / 32;
    {
        uint32_t dstb = base_u;
        for (int i = tid; i < 1024; i += 256) {
            int p = i >> 9, row = (i >> 2) & 127, seg = i & 3;
            cp16(dstb + p * PLANEB + row * ROWB + seg * 16,
                 pl[p] + (size_t)row * K + seg * 8);
        }
        cpcommit();
    }

    for (int s = 0; s < nst; s++) {
        cpwait<0>();
        __syncthreads();
        if (s + 1 < nst) {
            int kt = (s + 1) * 32;
            uint32_t dstb = base_u + ((s + 1) & 1) * STAGEB2;
            for (int i = tid; i < 1024; i += 256) {
                int p = i >> 9, row = (i >> 2) & 127, seg = i & 3;
                cp16(dstb + p * PLANEB + row * ROWB + seg * 16,
                     pl[p] + (size_t)row * K + kt + seg * 8);
            }
            cpcommit();
        }
        const uint32_t sb = base_u + (s & 1) * STAGEB2;
#pragma unroll
        for (int kc = 0; kc < 2; kc++) {
            uint32_t ah[4][4];
#pragma unroll
            for (int mi = 0; mi < 4; mi++)
                ldsm4(ah[mi], sb + aoff0 + mi * (16 * ROWB) + kc * 32);
            uint32_t bh[4][2];
#pragma unroll
            for (int p = 0; p < 2; p++) {
                uint32_t r[4];
                ldsm4(r, sb + PLANEB + boff0 + p * (16 * ROWB) + kc * 32);
                bh[2 * p][0] = r[0]; bh[2 * p][1] = r[1];
                bh[2 * p + 1][0] = r[2]; bh[2 * p + 1][1] = r[3];
            }
#pragma unroll
            for (int mi = 0; mi < 4; mi++)
#pragma unroll
                for (int nj = 0; nj < 4; nj++)
                    mma_f16(acc[mi][nj], ah[mi], bh[nj]);
        }
    }

    const int rfrag = lane >> 2;
    const int cpair = (lane & 3) * 2;

    if (bx < 24) {
        // ---- fused RMSNorm + RoPE epilogue ----
        __syncthreads();
        float* red = (float*)hsm;               // [128][4]
        float* xs  = (float*)(hsm + 2048);      // [128] rows, stride 132
        const float* w = (bx < 16) ? qw : kw;

#pragma unroll
        for (int mi = 0; mi < 4; mi++) {
#pragma unroll
            for (int half = 0; half < 2; half++) {
                float sq = 0.0f;
#pragma unroll
                for (int nj = 0; nj < 4; nj++) {
                    float a0 = acc[mi][nj][2 * half], a1 = acc[mi][nj][2 * half + 1];
                    sq += a0 * a0 + a1 * a1;
                }
                sq += __shfl_xor_sync(0xffffffffu, sq, 1);
                sq += __shfl_xor_sync(0xffffffffu, sq, 2);
                if ((lane & 3) == 0) {
                    int rloc = wm * 64 + mi * 16 + half * 8 + rfrag;
                    red[rloc * 4 + wn] = sq;
                }
            }
        }
        __syncthreads();

#pragma unroll
        for (int mi = 0; mi < 4; mi++) {
#pragma unroll
            for (int half = 0; half < 2; half++) {
                int rloc = wm * 64 + mi * 16 + half * 8 + rfrag;
                float sum = red[rloc * 4 + 0] + red[rloc * 4 + 1]
                          + red[rloc * 4 + 2] + red[rloc * 4 + 3];
                float rs = rsqrtf(sum * (1.0f / HD) + KEPS);
#pragma unroll
                for (int nj = 0; nj < 4; nj++) {
                    int d = wn * 32 + nj * 8 + cpair;
                    float v0 = acc[mi][nj][2 * half]     * rs * w[d];
                    float v1 = acc[mi][nj][2 * half + 1] * rs * w[d + 1];
                    acc[mi][nj][2 * half]     = v0;
                    acc[mi][nj][2 * half + 1] = v1;
                    xs[rloc * 132 + d]     = v0;
                    xs[rloc * 132 + d + 1] = v1;
                }
            }
        }
        __syncthreads();

        const float QSC = 0.08838834764831845f * 1.44269504088896341f;
#pragma unroll
        for (int mi = 0; mi < 4; mi++) {
#pragma unroll
            for (int half = 0; half < 2; half++) {
                int rloc = wm * 64 + mi * 16 + half * 8 + rfrag;
                int srow = blockIdx.y * 128 + rloc;
#pragma unroll
                for (int nj = 0; nj < 4; nj++) {
                    int d = wn * 32 + nj * 8 + cpair;
                    float2 cc = *(const float2*)(cosb + (size_t)srow * HD + d);
                    float2 ss = *(const float2*)(sinb + (size_t)srow * HD + d);
                    float p0 = xs[rloc * 132 + (d ^ 64)];
                    float p1 = xs[rloc * 132 + ((d ^ 64) + 1)];
                    float sgn = (d < 64) ? -1.0f : 1.0f;
                    float o0 = acc[mi][nj][2 * half]     * cc.x + sgn * p0 * ss.x;
                    float o1 = acc[mi][nj][2 * half + 1] * cc.y + sgn * p1 * ss.y;
                    if (bx < 16) {
                        *(uint32_t*)(qh + ((size_t)bx * Q + srow) * HD + d) =
                            cvt2h(o0 * QSC, o1 * QSC);
                    } else {
                        int kv = bx - 16;
                        *(float2*)(newK + ((size_t)kv * Q + srow) * HD + d) =
                            make_float2(o0, o1);
                        *(uint32_t*)(kh + ((size_t)kv * KVLEN + PAST + srow) * HD + d) =
                            cvt2h(o0, o1);
                    }
                }
            }
        }
    } else {
        // ---- V epilogue ----
#pragma unroll
        for (int mi = 0; mi < 4; mi++) {
#pragma unroll
            for (int nj = 0; nj < 4; nj++) {
                int d = wn * 32 + nj * 8 + cpair;
#pragma unroll
                for (int half = 0; half < 2; half++) {
                    int rowg = blockIdx.y * 128 + wm * 64 + mi * 16 + rfrag + half * 8;
                    float2 v = make_float2(acc[mi][nj][2 * half], acc[mi][nj][2 * half + 1]);
                    int kv = bx - 24;
                    *(float2*)(newV + (size_t)kv * (Q * HD) + (size_t)rowg * HD + d) = v;
                    size_t de = (size_t)kv * (KVLEN * HD) + (size_t)(PAST + rowg) * HD + d;
                    *(uint32_t*)(vph + de) = cvt2h(v.x, v.y);
                }
            }
        }
    }
}

// ---------------- output projection GEMM (128x128, 2 CTAs/SM residency) ----------------
__global__ __launch_bounds__(256, 2) void hgemm_o(
    const h16* __restrict__ Ah, const h16* __restrict__ Bh,
    float* __restrict__ C)
{
    extern __shared__ char hsm[];
    const int tid = threadIdx.x;
    const int lane = tid & 31;
    const int wid = tid >> 5;
    const int wm = wid >> 2;
    const int wn = wid & 3;
    const uint32_t base_u = smem_u32(hsm);
    const int K = NH * HD, N = NH * HD;

    const h16* pl[2] = {
        Ah + (size_t)(blockIdx.y * 128) * K,
        Bh + (size_t)(blockIdx.x * 128) * K };

    const int rowselA = lane & 15;
    const int halfA = lane >> 4;
    const int rowselB = (lane & 7) + (lane >> 4) * 8;
    const int halfB = (lane >> 3) & 1;
    const uint32_t aoff0 = (uint32_t)((wm * 64 + rowselA) * ROWB + halfA * 16);
    const uint32_t boff0 = (uint32_t)((wn * 32 + rowselB) * ROWB + halfB * 16);

    float acc[4][4][4];
#pragma unroll
    for (int i = 0; i < 4; i++)
#pragma unroll
        for (int j = 0; j < 4; j++)
#pragma unroll
            for (int r = 0; r < 4; r++) acc[i][j][r] = 0.0f;

    const int nst = K / 32;
    {
        uint32_t dstb = base_u;
        for (int i = tid; i < 1024; i += 256) {
            int p = i >> 9, row = (i >> 2) & 127, seg = i & 3;
            cp16(dstb + p * PLANEB + row * ROWB + seg * 16,
                 pl[p] + (size_t)row * K + seg * 8);
        }
        cpcommit();
    }

    for (int s = 0; s < nst; s++) {
        cpwait<0>();
        __syncthreads();
        if (s + 1 < nst) {
            int kt = (s + 1) * 32;
            uint32_t dstb = base_u + ((s + 1) & 1) * STAGEB2;
            for (int i = tid; i < 1024; i += 256) {
                int p = i >> 9, row = (i >> 2) & 127, seg = i & 3;
                cp16(dstb + p * PLANEB + row * ROWB + seg * 16,
                     pl[p] + (size_t)row * K + kt + seg * 8);
            }
            cpcommit();
        }
        const uint32_t sb = base_u + (s & 1) * STAGEB2;
#pragma unroll
        for (int kc = 0; kc < 2; kc++) {
            uint32_t ah[4][4];
#pragma unroll
            for (int mi = 0; mi < 4; mi++)
                ldsm4(ah[mi], sb + aoff0 + mi * (16 * ROWB) + kc * 32);
            uint32_t bh[4][2];
#pragma unroll
            for (int p = 0; p < 2; p++) {
                uint32_t r[4];
                ldsm4(r, sb + PLANEB + boff0 + p * (16 * ROWB) + kc * 32);
                bh[2 * p][0] = r[0]; bh[2 * p][1] = r[1];
                bh[2 * p + 1][0] = r[2]; bh[2 * p + 1][1] = r[3];
            }
#pragma unroll
            for (int mi = 0; mi < 4; mi++)
#pragma unroll
                for (int nj = 0; nj < 4; nj++)
                    mma_f16(acc[mi][nj], ah[mi], bh[nj]);
        }
    }

    const int rfrag = lane >> 2;
    const int cpair = (lane & 3) * 2;
#pragma unroll
    for (int mi = 0; mi < 4; mi++) {
#pragma unroll
        for (int nj = 0; nj < 4; nj++) {
            int colg = blockIdx.x * 128 + wn * 32 + nj * 8 + cpair;
#pragma unroll
            for (int half = 0; half < 2; half++) {
                int rowg = blockIdx.y * 128 + wm * 64 + mi * 16 + rfrag + half * 8;
                *(float2*)(C + (size_t)rowg * N + colg) =
                    make_float2(acc[mi][nj][2 * half], acc[mi][nj][2 * half + 1]);
            }
        }
    }
}

// ---------------- Flash attention: TQ=64, 128 threads, 2 CTAs/SM ----------------
#define AT_TQ 64
#define AT_TK 64
#define KVROW 272
#define KVPLANE (64 * KVROW)
#define TILEBUF (2 * KVPLANE)
#define AT_SMEM (2 * TILEBUF)

__global__ __launch_bounds__(128, 2) void attn_mma(
    const h16* __restrict__ qh,
    const h16* __restrict__ kch, const h16* __restrict__ vch,
    h16* __restrict__ aoh)
{
    extern __shared__ char asmem[];
    const int h = blockIdx.x;
    const int q0 = ((int)gridDim.y - 1 - (int)blockIdx.y) * AT_TQ;  // largest-first
    const int kvh = h >> 1;
    const int tid = threadIdx.x;
    const int lane = tid & 31;
    const int wid = tid >> 5;
    const uint32_t sb = smem_u32(asmem);

    {
        const h16* qsrc = qh + ((size_t)h * Q + q0) * HD;
        for (int i = tid; i < 1024; i += 128) {
            int row = i >> 4, seg = i & 15;
            cp16(sb + row * KVROW + seg * 16, qsrc + (size_t)row * HD + seg * 8);
        }
        cpcommit();
        cpwait<0>();
        __syncthreads();
    }
    uint32_t aQh[8][4];
    {
        uint32_t a0 = sb + (wid * 16 + (lane & 15)) * KVROW + (lane >> 4) * 16;
#pragma unroll
        for (int kc = 0; kc < 8; kc++)
            ldsm4(aQh[kc], a0 + kc * 32);
    }
    __syncthreads();

    float oacc[16][4];
#pragma unroll
    for (int f = 0; f < 16; f++)
#pragma unroll
        for (int r = 0; r < 4; r++) oacc[f][r] = 0.0f;
    float m0 = -1e30f, m1 = -1e30f, l0 = 0.0f, l1 = 0.0f;

    const int nt = (PAST + q0 + AT_TQ) / AT_TK;
    const h16* ksrc = kch + (size_t)kvh * KVLEN * HD;
    const h16* vsrc = vch + (size_t)kvh * KVLEN * HD;

    {
        for (int i = tid; i < 2048; i += 128) {
            int p = i >> 10, row = (i >> 4) & 63, seg = i & 15;
            const h16* s0 = p ? vsrc : ksrc;
            cp16(sb + p * KVPLANE + row * KVROW + seg * 16,
                 s0 + (size_t)row * HD + seg * 8);
        }
        cpcommit();
    }

    const int rowselB = (lane & 7) + (lane >> 4) * 8;
    const int halfB = (lane >> 3) & 1;
    const int rowV = lane & 15;
    const int halfV = (lane >> 4) * 16;

    for (int t = 0; t < nt; t++) {
        __syncthreads();
        if (t + 1 < nt) {
            int j1 = (t + 1) * AT_TK;
            uint32_t db = sb + ((t + 1) & 1) * TILEBUF;
            for (int i = tid; i < 2048; i += 128) {
                int p = i >> 10, row = (i >> 4) & 63, seg = i & 15;
                const h16* s0 = p ? vsrc : ksrc;
                cp16(db + p * KVPLANE + row * KVROW + seg * 16,
                     s0 + (size_t)(j1 + row) * HD + seg * 8);
            }
            cpcommit();
            cpwait<1>();
        } else {
            cpwait<0>();
        }
        __syncthreads();

        const uint32_t kb = sb + (t & 1) * TILEBUF;
        const int j0 = t * AT_TK;

        float sacc[8][4];
#pragma unroll
        for (int j = 0; j < 8; j++)
#pragma unroll
            for (int r = 0; r < 4; r++) sacc[j][r] = 0.0f;
#pragma unroll
        for (int kc = 0; kc < 8; kc++) {
#pragma unroll
            for (int nj = 0; nj < 4; nj++) {
                uint32_t kh[4];
                ldsm4(kh, kb + (nj * 16 + rowselB) * KVROW + halfB * 16 + kc * 32);
                mma_f16(sacc[2 * nj],     aQh[kc], kh);
                mma_f16(sacc[2 * nj + 1], aQh[kc], kh + 2);
            }
        }

        if (j0 + AT_TK - 1 > PAST + q0 + wid * 16) {
            int r0g = PAST + q0 + wid * 16 + (lane >> 2);
#pragma unroll
            for (int j = 0; j < 8; j++) {
                int cg = j0 + j * 8 + (lane & 3) * 2;
                if (cg > r0g)     sacc[j][0] = -1e30f;
                if (cg + 1 > r0g) sacc[j][1] = -1e30f;
                if (cg > r0g + 8)     sacc[j][2] = -1e30f;
                if (cg + 1 > r0g + 8) sacc[j][3] = -1e30f;
            }
        }

        float t0 = -1e30f, t1 = -1e30f;
#pragma unroll
        for (int j = 0; j < 8; j++) {
            t0 = fmaxf(t0, fmaxf(sacc[j][0], sacc[j][1]));
            t1 = fmaxf(t1, fmaxf(sacc[j][2], sacc[j][3]));
        }
        t0 = fmaxf(t0, __shfl_xor_sync(0xffffffffu, t0, 1));
        t0 = fmaxf(t0, __shfl_xor_sync(0xffffffffu, t0, 2));
        t1 = fmaxf(t1, __shfl_xor_sync(0xffffffffu, t1, 1));
        t1 = fmaxf(t1, __shfl_xor_sync(0xffffffffu, t1, 2));
        float mn0 = fmaxf(m0, t0), mn1 = fmaxf(m1, t1);
        float c0 = ex2(m0 - mn0), c1 = ex2(m1 - mn1);
        m0 = mn0; m1 = mn1;
        float ps0 = 0.0f, ps1 = 0.0f;
#pragma unroll
        for (int j = 0; j < 8; j++) {
            sacc[j][0] = ex2(sacc[j][0] - mn0); ps0 += sacc[j][0];
            sacc[j][1] = ex2(sacc[j][1] - mn0); ps0 += sacc[j][1];
            sacc[j][2] = ex2(sacc[j][2] - mn1); ps1 += sacc[j][2];
            sacc[j][3] = ex2(sacc[j][3] - mn1); ps1 += sacc[j][3];
        }
        ps0 += __shfl_xor_sync(0xffffffffu, ps0, 1);
        ps0 += __shfl_xor_sync(0xffffffffu, ps0, 2);
        ps1 += __shfl_xor_sync(0xffffffffu, ps1, 1);
        ps1 += __shfl_xor_sync(0xffffffffu, ps1, 2);
        l0 = l0 * c0 + ps0;
        l1 = l1 * c1 + ps1;

        unsigned need = __ballot_sync(0xffffffffu, (c0 != 1.0f) || (c1 != 1.0f));
        if (need) {
#pragma unroll
            for (int f = 0; f < 16; f++) {
                oacc[f][0] *= c0; oacc[f][1] *= c0;
                oacc[f][2] *= c1; oacc[f][3] *= c1;
            }
        }

        uint32_t pP[4][4];
#pragma unroll
        for (int kc = 0; kc < 4; kc++) {
            pP[kc][0] = cvt2h(sacc[2 * kc][0],     sacc[2 * kc][1]);
            pP[kc][1] = cvt2h(sacc[2 * kc][2],     sacc[2 * kc][3]);
            pP[kc][2] = cvt2h(sacc[2 * kc + 1][0], sacc[2 * kc + 1][1]);
            pP[kc][3] = cvt2h(sacc[2 * kc + 1][2], sacc[2 * kc + 1][3]);
        }

        const uint32_t vb = kb + KVPLANE;
#pragma unroll
        for (int kc = 0; kc < 4; kc++) {
#pragma unroll
            for (int dj = 0; dj < 8; dj++) {
                uint32_t vh[4];
                ldsm4t(vh, vb + (kc * 16 + rowV) * KVROW + dj * 32 + halfV);
                mma_f16(oacc[2 * dj],     pP[kc], vh);
                mma_f16(oacc[2 * dj + 1], pP[kc], vh + 2);
            }
        }
    }

    float inv0 = 1.0f / l0, inv1 = 1.0f / l1;
    int r0 = q0 + wid * 16 + (lane >> 2);
#pragma unroll
    for (int f = 0; f < 16; f++) {
        int d = f * 8 + (lane & 3) * 2;
        size_t e0 = (size_t)r0 * (NH * HD) + h * HD + d;
        size_t e1 = e0 + (size_t)8 * (NH * HD);
        *(uint32_t*)(aoh + e0) = cvt2h(oacc[f][0] * inv0, oacc[f][1] * inv0);
        *(uint32_t*)(aoh + e1) = cvt2h(oacc[f][2] * inv1, oacc[f][3] * inv1);
    }
}

// ---------------- launch ----------------
extern "C" void kernel_launch(void* const* d_in, const int* in_sizes, int n_in,
                              void* d_out, int out_size)
{
    const float* hs    = (const float*)d_in[0];
    const float* cosb  = (const float*)d_in[1];
    const float* sinb  = (const float*)d_in[2];
    const float* pastK = (const float*)d_in[4];
    const float* pastV = (const float*)d_in[5];
    const float* Wq    = (const float*)d_in[6];
    const float* Wk    = (const float*)d_in[7];
    const float* Wv    = (const float*)d_in[8];
    const float* Wo    = (const float*)d_in[9];
    const float* qw    = (const float*)d_in[10];
    const float* kw    = (const float*)d_in[11];

    float* out  = (float*)d_out;
    float* newK = out + (size_t)Q * NH * HD;
    float* newV = newK + (size_t)NKV * Q * HD;

    h16 *hsh, *wqh, *wkh, *wvh, *woh;
    h16 *qph, *kph, *vph, *aoh;
    cudaGetSymbolAddress((void**)&hsh, g_hs_h);
    cudaGetSymbolAddress((void**)&wqh, g_wq_h);
    cudaGetSymbolAddress((void**)&wkh, g_wk_h);
    cudaGetSymbolAddress((void**)&wvh, g_wv_h);
    cudaGetSymbolAddress((void**)&woh, g_wo_h);
    cudaGetSymbolAddress((void**)&qph, g_q_h);
    cudaGetSymbolAddress((void**)&kph, g_k_h);
    cudaGetSymbolAddress((void**)&vph, g_v_h);
    cudaGetSymbolAddress((void**)&aoh, g_ao_h);

    cudaFuncSetAttribute(hgemm_qkv, cudaFuncAttributeMaxDynamicSharedMemorySize, QKV_SMEM);
    cudaFuncSetAttribute(hgemm_o, cudaFuncAttributeMaxDynamicSharedMemorySize, HO_SMEM);
    cudaFuncSetAttribute(attn_mma, cudaFuncAttributeMaxDynamicSharedMemorySize, AT_SMEM);

    // merged convert (8 virtual blocks per real block)
    kconv_all<<<2560, 256>>>(hs, hsh, Wq, wqh, Wk, wkh, Wv, wvh, Wo, woh,
                             pastK, kph, pastV, vph);

    // fused QKV projection + RMSNorm + RoPE
    hgemm_qkv<<<dim3(32, Q / 128), 256, QKV_SMEM>>>(
        hsh, wqh, wkh, wvh, cosb, sinb, qw, kw, qph, kph, newK, newV, vph);

    // attention (TQ=64, 2 CTAs/SM)
    attn_mma<<<dim3(NH, Q / AT_TQ), 128, AT_SMEM>>>(qph, kph, vph, aoh);

    // output projection (128x128, 2 CTAs/SM residency)
    hgemm_o<<<dim3(NH * HD / 128, Q / 128), 256, HO_SMEM>>>(aoh, woh, out);
}